// round 17
// baseline (speedup 1.0000x reference)
#include <cuda_runtime.h>
#include <cuda_fp16.h>
#include <math.h>
#include <stdint.h>

#define Bn 4096
#define Fdim 512
#define Hdim 1024
#define Nn 64
#define Dd 64
#define FLAT 4096
#define Ccls 1000
#define CAP 64
#define Pp 8

// ================= scratch (device globals) =================
__device__ float g_h1[Bn * Hdim];
__device__ float g_b2a[FLAT];
__device__ float g_xagg[(size_t)Bn * FLAT];
__device__ float g_sim[Bn * CAP];
__device__ float g_s1[Bn * Hdim];
__device__ float g_bcat[2048];
__device__ float g_WcT[Nn * Dd * Dd];
__device__ float g_cf[Nn * Dd];
// fp16 hi/lo operand buffers
__device__ __half g_xh[Bn * Fdim],    g_xl[Bn * Fdim];
__device__ __half g_W1h[Hdim * Fdim], g_W1l[Hdim * Fdim];
__device__ __half g_h1h[Bn * Hdim],   g_h1l[Bn * Hdim];
__device__ __half g_W2h[FLAT * Hdim], g_W2l[FLAT * Hdim];
__device__ __half g_xfh[(size_t)Bn * FLAT], g_xfl[(size_t)Bn * FLAT];
__device__ __half g_Wcath[(size_t)2048 * FLAT];
__device__ __half g_memh[128 * FLAT], g_meml[128 * FLAT];

__device__ __forceinline__ float sigmoidf_(float x) { return 1.f / (1.f + expf(-x)); }

__device__ __forceinline__ uint32_t pack2h(__half a, __half b) {
    return (uint32_t)__half_as_ushort(a) | ((uint32_t)__half_as_ushort(b) << 16);
}
__device__ __forceinline__ void cvt4(float4 v, uint2& hi, uint2& lo) {
    __half h0 = __float2half_rn(v.x), h1 = __float2half_rn(v.y);
    __half h2 = __float2half_rn(v.z), h3 = __float2half_rn(v.w);
    __half l0 = __float2half_rn(v.x - __half2float(h0));
    __half l1 = __float2half_rn(v.y - __half2float(h1));
    __half l2 = __float2half_rn(v.z - __half2float(h2));
    __half l3 = __float2half_rn(v.w - __half2float(h3));
    hi.x = pack2h(h0, h1); hi.y = pack2h(h2, h3);
    lo.x = pack2h(l0, l1); lo.y = pack2h(l2, l3);
}
__device__ __forceinline__ uint2 cvt4hi(float4 v) {
    __half h0 = __float2half_rn(v.x), h1 = __float2half_rn(v.y);
    __half h2 = __float2half_rn(v.z), h3 = __float2half_rn(v.w);
    uint2 hi; hi.x = pack2h(h0, h1); hi.y = pack2h(h2, h3);
    return hi;
}
__device__ __forceinline__ void cvt2(float a, float b, uint32_t& hi, uint32_t& lo) {
    __half h0 = __float2half_rn(a), h1 = __float2half_rn(b);
    __half l0 = __float2half_rn(a - __half2float(h0));
    __half l1 = __float2half_rn(b - __half2float(h1));
    hi = pack2h(h0, h1); lo = pack2h(l0, l1);
}

// ================= packed f32x2 FMA (Blackwell) =================
#define FMA_F32X2(d, a, b) \
    asm("fma.rn.f32x2 %0, %1, %2, %0;" : "+l"(d) : "l"(a), "l"(b))
#define PACKF2(out, a, b) \
    asm("mov.b64 %0, {%1, %2};" : "=l"(out) : "f"(a), "f"(b))
#define UNPACKF2(a, b, in) \
    asm("mov.b64 {%0, %1}, %2;" : "=f"(a), "=f"(b) : "l"(in))

// ================= mma / cp.async / ldmatrix primitives =================
__device__ __forceinline__ uint32_t smem_u32(const void* p) {
    uint32_t a;
    asm("{ .reg .u64 t; cvta.to.shared.u64 t, %1; cvt.u32.u64 %0, t; }" : "=r"(a) : "l"(p));
    return a;
}
__device__ __forceinline__ void cp16(uint32_t s, const void* g) {
    asm volatile("cp.async.cg.shared.global [%0], [%1], 16;" :: "r"(s), "l"(g));
}
#define CP_COMMIT() asm volatile("cp.async.commit_group;")
#define CP_WAIT1() asm volatile("cp.async.wait_group 1;")

__device__ __forceinline__ void mma16816(float* d, const uint32_t* a, uint32_t b0, uint32_t b1) {
    asm volatile(
        "mma.sync.aligned.m16n8k16.row.col.f32.f16.f16.f32 "
        "{%0,%1,%2,%3}, {%4,%5,%6,%7}, {%8,%9}, {%0,%1,%2,%3};"
        : "+f"(d[0]), "+f"(d[1]), "+f"(d[2]), "+f"(d[3])
        : "r"(a[0]), "r"(a[1]), "r"(a[2]), "r"(a[3]), "r"(b0), "r"(b1));
}
__device__ __forceinline__ void ldsm_x4(uint32_t& r0, uint32_t& r1, uint32_t& r2, uint32_t& r3,
                                        uint32_t addr) {
    asm volatile("ldmatrix.sync.aligned.m8n8.x4.shared.b16 {%0,%1,%2,%3}, [%4];"
                 : "=r"(r0), "=r"(r1), "=r"(r2), "=r"(r3) : "r"(addr));
}

// ================= fused prep mega-kernel =================
#define MISC_BLOCKS 12424

__global__ void __launch_bounds__(256) misc_prep(
    const float* __restrict__ x, const float* __restrict__ W1,
    const float* __restrict__ Ws1, const float* __restrict__ mem,
    const float* __restrict__ Wh, const float* __restrict__ bh,
    const float* __restrict__ bs1, const float* __restrict__ b2,
    const float* __restrict__ edge_w, const float* __restrict__ mask,
    const float* __restrict__ Wslow, const float* __restrict__ u,
    const float* __restrict__ Wfast, const float* __restrict__ Wf,
    const float* __restrict__ bf, const float* __restrict__ hprev) {
    const int bid = blockIdx.x;
    const int tid = threadIdx.x;

    if (bid < 2048) {
        int i = bid * 256 + tid;
        float4 v = ((const float4*)x)[i];
        uint2 h, l; cvt4(v, h, l);
        ((uint2*)g_xh)[i] = h; ((uint2*)g_xl)[i] = l;
    } else if (bid < 2560) {
        int i = (bid - 2048) * 256 + tid;
        float4 v = ((const float4*)W1)[i];
        uint2 h, l; cvt4(v, h, l);
        ((uint2*)g_W1h)[i] = h; ((uint2*)g_W1l)[i] = l;
    } else if (bid < 6656) {
        int i = (bid - 2560) * 256 + tid;
        float4 v = ((const float4*)Ws1)[i];
        ((uint2*)g_Wcath)[(1024 * FLAT / 4) + i] = cvt4hi(v);
    } else if (bid < 7168) {
        int i = (bid - 6656) * 256 + tid;
        int row = i >> 10;
        uint2 h = make_uint2(0u, 0u), l = make_uint2(0u, 0u);
        if (row < CAP) {
            float4 v = ((const float4*)mem)[i];
            cvt4(v, h, l);
        }
        ((uint2*)g_memh)[i] = h; ((uint2*)g_meml)[i] = l;
    } else if (bid < 11264) {
        int i = (bid - 7168) * 256 + tid;
        int row = i >> 10;
        uint2 h = make_uint2(0u, 0u);
        if (row < Ccls) {
            const size_t CF4 = (size_t)Ccls * FLAT / 4;
            const float4* W4 = (const float4*)Wh;
            float4 a = W4[i], b = W4[i + CF4], c = W4[i + 2 * CF4];
            float4 m = make_float4((a.x + b.x + c.x) * (1.f / 3.f), (a.y + b.y + c.y) * (1.f / 3.f),
                                   (a.z + b.z + c.z) * (1.f / 3.f), (a.w + b.w + c.w) * (1.f / 3.f));
            h = cvt4hi(m);
        }
        ((uint2*)g_Wcath)[i] = h;
    } else if (bid < 11272) {
        int i = (bid - 11264) * 256 + tid;
        if (i < 2048) {
            float v;
            if (i < Ccls) v = (bh[i] + bh[i + Ccls] + bh[i + 2 * Ccls]) * (1.f / 3.f);
            else if (i < 1024) v = 0.f;
            else v = bs1[i - 1024];
            g_bcat[i] = v;
        }
    } else if (bid < 12296) {
        g_sim[(bid - 11272) * 256 + tid] = 0.f;
    } else if (bid < 12360) {
        __shared__ float rowv[64];
        int n = bid - 12296;
        if (tid == 0) {
            float sum = 0.f;
            for (int c = 0; c < 64; c++) {
                float v = sigmoidf_(edge_w[n * 64 + c] * 1.5f) * mask[n * 64 + c];
                rowv[c] = v; sum += v;
            }
            float inv = 1.f / fmaxf(sum, 1e-6f);
            for (int c = 0; c < 64; c++) rowv[c] = rowv[c] * inv;
        }
        __syncthreads();
        if (tid < 64) {
            int d = tid;
            float acc = 0.f;
            for (int m = 0; m < 64; m++) acc += rowv[m] * b2[m * 64 + d];
            g_b2a[n * 64 + d] = acc;
        }
    } else {
        __shared__ float us[64], v[64], red[64];
        int n = bid - 12360;
        int t = tid;
        const float* Ws = Wslow + (size_t)n * 4096;
        if (t < 64) us[t] = u[n * 64 + t];
        __syncthreads();
        if (t < 64) {
            float acc = 0.f;
            for (int o = 0; o < 64; o++) acc += Ws[o * 64 + t] * us[o];
            v[t] = acc;
        }
        __syncthreads();
        if (t < 64) {
            float wv = 0.f;
            for (int i = 0; i < 64; i++) wv += Ws[t * 64 + i] * v[i];
            red[t] = us[t] * wv;
        }
        __syncthreads();
        for (int off = 32; off > 0; off >>= 1) {
            if (t < off) red[t] += red[t + off];
            __syncthreads();
        }
        float inv = 1.f / (red[0] + 1e-8f);
        const float* Wfa = Wfast + (size_t)n * 4096;
        float* outp = g_WcT + (size_t)n * 4096;
        for (int idx = t; idx < 4096; idx += 256) {
            int i = idx >> 6, o = idx & 63;
            outp[idx] = Ws[o * 64 + i] * inv + Wfa[o * 64 + i];
        }
        if (t < 64) {
            float c = bf[n * 64 + t];
            const float* Wf2 = Wf + (size_t)n * 8192 + 4096;
            for (int i = 0; i < 64; i++) c += hprev[n * 64 + i] * Wf2[i * 64 + t];
            g_cf[n * 64 + t] = c;
        }
    }
}

// ================= fold W2 (in-kernel adjacency, bit-exact) =================
__global__ void __launch_bounds__(256) fold_w2(const float* __restrict__ W2,
                                               const float* __restrict__ edge_w,
                                               const float* __restrict__ mask) {
    int kt = blockIdx.x;
    int d  = blockIdx.y;
    __shared__ float tile[64][128];
    __shared__ float adjT[64 * 64];
    int tid = threadIdx.x;
    if (tid < 64) {
        int r = tid;
        float sum = 0.f;
        for (int c = 0; c < 64; c++) {
            float v = sigmoidf_(edge_w[r * 64 + c] * 1.5f) * mask[r * 64 + c];
            adjT[c * 64 + r] = v; sum += v;
        }
        float inv = 1.f / fmaxf(sum, 1e-6f);
        for (int c = 0; c < 64; c++) adjT[c * 64 + r] = adjT[c * 64 + r] * inv;
    }
    for (int i = tid; i < 64 * 32; i += 256) {
        int m = i >> 5, c4 = (i & 31) << 2;
        *(float4*)&tile[m][c4] = *(const float4*)(W2 + (size_t)(m * 64 + d) * Hdim + kt * 128 + c4);
    }
    __syncthreads();
    int n = tid & 63;
    int kq = tid >> 6;
    float4 acc[8];
#pragma unroll
    for (int q = 0; q < 8; q++) acc[q] = make_float4(0.f, 0.f, 0.f, 0.f);
    for (int m = 0; m < 64; m++) {
        float s = adjT[m * 64 + n];
        const float4* trow = (const float4*)&tile[m][kq * 32];
#pragma unroll
        for (int q = 0; q < 8; q++) {
            float4 t4 = trow[q];
            acc[q].x += s * t4.x; acc[q].y += s * t4.y;
            acc[q].z += s * t4.z; acc[q].w += s * t4.w;
        }
    }
    size_t off4 = ((size_t)(n * 64 + d) * Hdim + kt * 128 + kq * 32) >> 2;
#pragma unroll
    for (int q = 0; q < 8; q++) {
        uint2 h, l; cvt4(acc[q], h, l);
        ((uint2*)g_W2h)[off4 + q] = h;
        ((uint2*)g_W2l)[off4 + q] = l;
    }
}

// ================= split-fp16 HMMA GEMM (persistent tiles; act==2 dual output) =================
#define TSTRIDE 40
#define ROWB (TSTRIDE * 2)
#define TILE_B (128 * ROWB)
#define STAGE_B (4 * TILE_B)
#define GSMEM_TOTAL (2 * STAGE_B)

template <int NI, int PASSES>
__global__ void __launch_bounds__(256, 2) gemm_mma(
    const __half* __restrict__ Ahi, const __half* __restrict__ Alo,
    const __half* __restrict__ Bhi, const __half* __restrict__ Blo,
    const float* __restrict__ bias, float* __restrict__ C, float* __restrict__ C2,
    int K, int lda, int Nstore, int act, int atomicOut,
    int tilesX, int tilesTotal) {
    extern __shared__ char smem[];
    const int tid = threadIdx.x;
    const int wid = tid >> 5;
    const int lane = tid & 31;
    const int grp = lane >> 2;
    const int qp = lane & 3;
    const int wm = (wid >> 2) * 64;
    const int wn = (wid & 3) * (NI * 8);
    const int kbase = blockIdx.z * K;
    const uint32_t sb = smem_u32(smem);

    const int row = tid >> 2;
    const int c16 = tid & 3;

    const int aRowL = wm + (lane & 7) + ((lane >> 3) & 1) * 8;
    const int aKL = (lane >> 4) * 8;
    const int bRowL = wn + (lane & 7) + (lane >> 4) * 8;
    const int bKL = ((lane >> 3) & 1) * 8;

    const int nc = K >> 5;

    for (int t = blockIdx.x; t < tilesTotal; t += gridDim.x) {
        const int bm = (t / tilesX) * 128;
        const int bn = (t % tilesX) * 128;
        __syncthreads();

        float acc[4][NI][4];
#pragma unroll
        for (int mi = 0; mi < 4; mi++)
#pragma unroll
            for (int ni = 0; ni < NI; ni++)
#pragma unroll
                for (int j = 0; j < 4; j++) acc[mi][ni][j] = 0.f;

        auto issue = [&](int c, int s) {
            const uint32_t ss = sb + s * STAGE_B;
            const int k0 = c << 5;
#pragma unroll
            for (int tt = 0; tt < 2; tt++) {
                const int r = row + tt * 64;
                const uint32_t so = (uint32_t)r * ROWB + c16 * 16;
                const size_t gAoff = ((size_t)(bm + r) * lda + kbase + k0) * 2 + c16 * 16;
                const size_t gBoff = ((size_t)(bn + r) * lda + kbase + k0) * 2 + c16 * 16;
                cp16(ss + 0 * TILE_B + so, (const char*)Ahi + gAoff);
                if (PASSES == 3) cp16(ss + 1 * TILE_B + so, (const char*)Alo + gAoff);
                cp16(ss + 2 * TILE_B + so, (const char*)Bhi + gBoff);
                if (PASSES >= 2) cp16(ss + 3 * TILE_B + so, (const char*)Blo + gBoff);
            }
        };

        issue(0, 0); CP_COMMIT();
        if (nc > 1) issue(1, 1);
        CP_COMMIT();

        for (int c = 0; c < nc; c++) {
            const int s = c & 1;
            CP_WAIT1();
            __syncthreads();
            const uint32_t st = sb + s * STAGE_B;
#pragma unroll
            for (int ks = 0; ks < 2; ks++) {
                const int k0 = ks * 16;
                uint32_t ah[4][4], al[4][4];
#pragma unroll
                for (int mi = 0; mi < 4; mi++) {
                    const uint32_t ad = st + (uint32_t)(aRowL + mi * 16) * ROWB + (k0 + aKL) * 2;
                    ldsm_x4(ah[mi][0], ah[mi][1], ah[mi][2], ah[mi][3], ad);
                    if (PASSES == 3) ldsm_x4(al[mi][0], al[mi][1], al[mi][2], al[mi][3], ad + TILE_B);
                }
                uint32_t bh[NI][2], bl[NI][2];
#pragma unroll
                for (int p = 0; p < NI / 2; p++) {
                    const uint32_t bd = st + 2 * TILE_B + (uint32_t)(bRowL + p * 16) * ROWB + (k0 + bKL) * 2;
                    uint32_t r0, r1, r2, r3;
                    ldsm_x4(r0, r1, r2, r3, bd);
                    bh[2 * p][0] = r0; bh[2 * p][1] = r1; bh[2 * p + 1][0] = r2; bh[2 * p + 1][1] = r3;
                    if (PASSES >= 2) {
                        ldsm_x4(r0, r1, r2, r3, bd + TILE_B);
                        bl[2 * p][0] = r0; bl[2 * p][1] = r1; bl[2 * p + 1][0] = r2; bl[2 * p + 1][1] = r3;
                    }
                }
#pragma unroll
                for (int ni = 0; ni < NI; ni++) {
#pragma unroll
                    for (int mi = 0; mi < 4; mi++) {
                        mma16816(acc[mi][ni], ah[mi], bh[ni][0], bh[ni][1]);
                        if (PASSES >= 2) mma16816(acc[mi][ni], ah[mi], bl[ni][0], bl[ni][1]);
                        if (PASSES == 3) mma16816(acc[mi][ni], al[mi], bh[ni][0], bh[ni][1]);
                    }
                }
            }
            __syncthreads();
            if (c + 2 < nc) issue(c + 2, s);
            CP_COMMIT();
        }

        // epilogue
#pragma unroll
        for (int mi = 0; mi < 4; mi++) {
#pragma unroll
            for (int ni = 0; ni < NI; ni++) {
                const int r0 = bm + wm + mi * 16 + grp;
                const int col = bn + wn + ni * 8 + qp * 2;
                float* a4 = acc[mi][ni];
                if (atomicOut) {
                    if (col < Nstore) {
                        atomicAdd(&C[(size_t)r0 * Nstore + col], a4[0]);
                        atomicAdd(&C[(size_t)(r0 + 8) * Nstore + col], a4[2]);
                        if (col + 1 < Nstore) {
                            atomicAdd(&C[(size_t)r0 * Nstore + col + 1], a4[1]);
                            atomicAdd(&C[(size_t)(r0 + 8) * Nstore + col + 1], a4[3]);
                        }
                    }
                } else if (act == 2) {
                    float bb0 = bias[col], bb1 = bias[col + 1];
                    if (col < 1024) {
                        if (col < 1000) {
                            float2 v0 = make_float2(a4[0] + bb0, a4[1] + bb1);
                            float2 v1 = make_float2(a4[2] + bb0, a4[3] + bb1);
                            *(float2*)(C + (size_t)r0 * 1000 + col) = v0;
                            *(float2*)(C + (size_t)(r0 + 8) * 1000 + col) = v1;
                        }
                    } else {
                        int c2 = col - 1024;
                        float2 v0 = make_float2(fmaxf(a4[0] + bb0, 0.f), fmaxf(a4[1] + bb1, 0.f));
                        float2 v1 = make_float2(fmaxf(a4[2] + bb0, 0.f), fmaxf(a4[3] + bb1, 0.f));
                        *(float2*)(C2 + (size_t)r0 * 1024 + c2) = v0;
                        *(float2*)(C2 + (size_t)(r0 + 8) * 1024 + c2) = v1;
                    }
                } else if (col + 1 < Nstore) {
                    float2 v0, v1;
                    float bb0 = bias ? bias[col] : 0.f;
                    float bb1 = bias ? bias[col + 1] : 0.f;
                    v0.x = a4[0] + bb0; v0.y = a4[1] + bb1;
                    v1.x = a4[2] + bb0; v1.y = a4[3] + bb1;
                    if (act == 1) {
                        v0.x = fmaxf(v0.x, 0.f); v0.y = fmaxf(v0.y, 0.f);
                        v1.x = fmaxf(v1.x, 0.f); v1.y = fmaxf(v1.y, 0.f);
                    }
                    *(float2*)(C + (size_t)r0 * Nstore + col) = v0;
                    *(float2*)(C + (size_t)(r0 + 8) * Nstore + col) = v1;
                } else if (col < Nstore) {
                    float bb0 = bias ? bias[col] : 0.f;
                    float v0 = a4[0] + bb0, v1 = a4[2] + bb0;
                    if (act == 1) { v0 = fmaxf(v0, 0.f); v1 = fmaxf(v1, 0.f); }
                    C[(size_t)r0 * Nstore + col] = v0;
                    C[(size_t)(r0 + 8) * Nstore + col] = v1;
                }
            }
        }
    }
}

// ================= LayerNorm(H=1024) + GELU -> fp16 hi/lo =================
__global__ void __launch_bounds__(256) ln_gelu_kernel(const float* __restrict__ h,
                                                      const float* __restrict__ g,
                                                      const float* __restrict__ beta,
                                                      uint2* __restrict__ hi,
                                                      uint2* __restrict__ lo) {
    int row = blockIdx.x;
    const float* hr = h + (size_t)row * Hdim;
    int tid = threadIdx.x;
    float4 v = *(const float4*)(hr + tid * 4);
    float s = v.x + v.y + v.z + v.w;
    float ss = v.x * v.x + v.y * v.y + v.z * v.z + v.w * v.w;
    __shared__ float rs[8], rss[8];
    for (int o = 16; o > 0; o >>= 1) {
        s += __shfl_down_sync(0xffffffffu, s, o);
        ss += __shfl_down_sync(0xffffffffu, ss, o);
    }
    if ((tid & 31) == 0) { rs[tid >> 5] = s; rss[tid >> 5] = ss; }
    __syncthreads();
    if (tid < 32) {
        float a = tid < 8 ? rs[tid] : 0.f;
        float b = tid < 8 ? rss[tid] : 0.f;
        for (int o = 4; o > 0; o >>= 1) {
            a += __shfl_down_sync(0xffffffffu, a, o);
            b += __shfl_down_sync(0xffffffffu, b, o);
        }
        if (tid == 0) { rs[0] = a; rss[0] = b; }
    }
    __syncthreads();
    float mu = rs[0] * (1.f / Hdim);
    float var = rss[0] * (1.f / Hdim) - mu * mu;
    float inv = rsqrtf(var + 1e-5f);
    float4 gg = *(const float4*)(g + tid * 4);
    float4 bb = *(const float4*)(beta + tid * 4);
    float y;
    y = (v.x - mu) * inv * gg.x + bb.x; v.x = 0.5f * y * (1.f + erff(y * 0.70710678118654752f));
    y = (v.y - mu) * inv * gg.y + bb.y; v.y = 0.5f * y * (1.f + erff(y * 0.70710678118654752f));
    y = (v.z - mu) * inv * gg.z + bb.z; v.z = 0.5f * y * (1.f + erff(y * 0.70710678118654752f));
    y = (v.w - mu) * inv * gg.w + bb.w; v.w = 0.5f * y * (1.f + erff(y * 0.70710678118654752f));
    uint2 hh, ll; cvt4(v, hh, ll);
    hi[(size_t)row * 256 + tid] = hh;
    lo[(size_t)row * 256 + tid] = ll;
}

// ================= fused cell kernel (weights resident; batch-tile loop) =================
#define CELL_SMEM ((64 * 68 * 2 + 4096 * 4 + 7 * 64) * sizeof(float))
#define CELL_SPLIT 4
__global__ void __launch_bounds__(256) cell_kernel(const float* __restrict__ Wi,
                                                   const float* __restrict__ Wf,
                                                   const float* __restrict__ Wo,
                                                   const float* __restrict__ bi_g,
                                                   const float* __restrict__ bslow_g,
                                                   const float* __restrict__ bo_g,
                                                   const float* __restrict__ hprev_g,
                                                   const float* __restrict__ gln_g,
                                                   const float* __restrict__ bln_g,
                                                   float* __restrict__ xflat_out,
                                                   uint32_t* __restrict__ xfh,
                                                   uint32_t* __restrict__ xfl) {
    extern __shared__ float sf[];
    float* xs = sf;
    float* wi = xs + 64 * 68;
    float* wf = wi + 4096;
    float* wc = wf + 4096;
    float* wo = wc + 4096;
    float* hr = wo + 4096;
    float* vecs = hr + 64 * 68;

    const int n = blockIdx.x;
    const int tid = threadIdx.x;

    // ---- load per-node weights + vectors ONCE ----
#pragma unroll
    for (int j = 0; j < 4; j++) {
        int idx = tid + j * 256;
        ((float4*)wi)[idx] = ((const float4*)(Wi + (size_t)n * 4096))[idx];
        ((float4*)wf)[idx] = ((const float4*)(Wf + (size_t)n * 8192))[idx];
        ((float4*)wc)[idx] = ((const float4*)(g_WcT + (size_t)n * 4096))[idx];
        ((float4*)wo)[idx] = ((const float4*)(Wo + (size_t)n * 4096))[idx];
    }
    if (tid < 64) {
        vecs[0 * 64 + tid] = bi_g[n * 64 + tid];
        vecs[1 * 64 + tid] = g_cf[n * 64 + tid];
        vecs[2 * 64 + tid] = bslow_g[n * 64 + tid];
        vecs[3 * 64 + tid] = bo_g[n * 64 + tid];
        vecs[4 * 64 + tid] = hprev_g[n * 64 + tid];
        vecs[5 * 64 + tid] = gln_g[n * 64 + tid];
        vecs[6 * 64 + tid] = bln_g[n * 64 + tid];
    }

    const int r0 = (tid >> 4) * 4;
    const int c0 = (tid & 15) * 4;
    const int w = tid >> 5, lane = tid & 31;

    for (int bt = blockIdx.y; bt < 64; bt += CELL_SPLIT) {
        const int b0 = bt * 64;
        __syncthreads();   // weights ready (first iter) / previous tile fully consumed

        // ---- load x_agg tile ----
#pragma unroll
        for (int j = 0; j < 4; j++) {
            int idx = tid + j * 256;
            int row = idx >> 4, c4 = (idx & 15) << 2;
            *(float4*)(xs + row * 68 + c4) =
                *(const float4*)(g_xagg + (((size_t)(b0 + row) * 64 + n) << 6) + c4);
        }
        __syncthreads();

        unsigned long long ai2[4][2], af2[4][2], ac2[4][2];
#pragma unroll
        for (int r = 0; r < 4; r++)
#pragma unroll
            for (int p = 0; p < 2; p++) { ai2[r][p] = 0ull; af2[r][p] = 0ull; ac2[r][p] = 0ull; }

        for (int i = 0; i < 64; i++) {
            unsigned long long xp[4];
#pragma unroll
            for (int r = 0; r < 4; r++) {
                float xv = xs[(r0 + r) * 68 + i];
                PACKF2(xp[r], xv, xv);
            }
            float4 w1 = *(const float4*)(wi + i * 64 + c0);
            float4 w2 = *(const float4*)(wf + i * 64 + c0);
            float4 w3 = *(const float4*)(wc + i * 64 + c0);
            unsigned long long w1p[2], w2p[2], w3p[2];
            PACKF2(w1p[0], w1.x, w1.y); PACKF2(w1p[1], w1.z, w1.w);
            PACKF2(w2p[0], w2.x, w2.y); PACKF2(w2p[1], w2.z, w2.w);
            PACKF2(w3p[0], w3.x, w3.y); PACKF2(w3p[1], w3.z, w3.w);
#pragma unroll
            for (int r = 0; r < 4; r++) {
                FMA_F32X2(ai2[r][0], xp[r], w1p[0]); FMA_F32X2(ai2[r][1], xp[r], w1p[1]);
                FMA_F32X2(af2[r][0], xp[r], w2p[0]); FMA_F32X2(af2[r][1], xp[r], w2p[1]);
                FMA_F32X2(ac2[r][0], xp[r], w3p[0]); FMA_F32X2(ac2[r][1], xp[r], w3p[1]);
            }
        }
#pragma unroll
        for (int r = 0; r < 4; r++)
#pragma unroll
            for (int p = 0; p < 2; p++) {
                float aiv0, aiv1, afv0, afv1, acv0, acv1;
                UNPACKF2(aiv0, aiv1, ai2[r][p]);
                UNPACKF2(afv0, afv1, af2[r][p]);
                UNPACKF2(acv0, acv1, ac2[r][p]);
                int o = c0 + 2 * p;
                float it0 = sigmoidf_(aiv0 + vecs[0 * 64 + o]);
                float ft0 = sigmoidf_(afv0 + vecs[1 * 64 + o]);
                float hs0 = acv0 + vecs[2 * 64 + o];
                hr[(r0 + r) * 68 + o] = it0 * hs0 + ft0 * vecs[4 * 64 + o];
                float it1 = sigmoidf_(aiv1 + vecs[0 * 64 + o + 1]);
                float ft1 = sigmoidf_(afv1 + vecs[1 * 64 + o + 1]);
                float hs1 = acv1 + vecs[2 * 64 + o + 1];
                hr[(r0 + r) * 68 + o + 1] = it1 * hs1 + ft1 * vecs[4 * 64 + o + 1];
            }
        __syncthreads();

        unsigned long long ao2[4][2];
#pragma unroll
        for (int r = 0; r < 4; r++)
#pragma unroll
            for (int p = 0; p < 2; p++) ao2[r][p] = 0ull;
        for (int i = 0; i < 64; i++) {
            unsigned long long xp[4];
#pragma unroll
            for (int r = 0; r < 4; r++) {
                float xv = hr[(r0 + r) * 68 + i];
                PACKF2(xp[r], xv, xv);
            }
            float4 wv4 = *(const float4*)(wo + i * 64 + c0);
            unsigned long long wp[2];
            PACKF2(wp[0], wv4.x, wv4.y); PACKF2(wp[1], wv4.z, wv4.w);
#pragma unroll
            for (int r = 0; r < 4; r++) {
                FMA_F32X2(ao2[r][0], xp[r], wp[0]);
                FMA_F32X2(ao2[r][1], xp[r], wp[1]);
            }
        }
        float* ys = xs;
#pragma unroll
        for (int r = 0; r < 4; r++)
#pragma unroll
            for (int p = 0; p < 2; p++) {
                float a0, a1;
                UNPACKF2(a0, a1, ao2[r][p]);
                int o = c0 + 2 * p;
                float ot0 = sigmoidf_(a0 + vecs[3 * 64 + o]);
                float ot1 = sigmoidf_(a1 + vecs[3 * 64 + o + 1]);
                ys[(r0 + r) * 68 + o] = ot0 * tanhf(hr[(r0 + r) * 68 + o]);
                ys[(r0 + r) * 68 + o + 1] = ot1 * tanhf(hr[(r0 + r) * 68 + o + 1]);
            }
        __syncthreads();

        for (int rr = 0; rr < 8; rr++) {
            int row = w * 8 + rr;
            float v0 = ys[row * 68 + 2 * lane];
            float v1 = ys[row * 68 + 2 * lane + 1];
            float s = v0 + v1;
            float ss = v0 * v0 + v1 * v1;
            for (int o = 16; o > 0; o >>= 1) {
                s += __shfl_xor_sync(0xffffffffu, s, o);
                ss += __shfl_xor_sync(0xffffffffu, ss, o);
            }
            float mu = s * (1.f / 64.f);
            float var = ss * (1.f / 64.f) - mu * mu;
            float inv = rsqrtf(var + 1e-5f);
            float y0 = (v0 - mu) * inv * vecs[5 * 64 + 2 * lane] + vecs[6 * 64 + 2 * lane];
            float y1 = (v1 - mu) * inv * vecs[5 * 64 + 2 * lane + 1] + vecs[6 * 64 + 2 * lane + 1];
            size_t base = (size_t)(b0 + row) * 4096 + n * 64;
            *(float2*)(xflat_out + base + 2 * lane) = make_float2(y0, y1);
            uint32_t hh, ll; cvt2(y0, y1, hh, ll);
            xfh[(base >> 1) + lane] = hh;
            xfl[(base >> 1) + lane] = ll;
        }
    }
}

// ================= top-5 retrieval + update + fp16 re-emit =================
__global__ void __launch_bounds__(256) retrieve_kernel(const float* __restrict__ mem,
                                                       float* __restrict__ xflat,
                                                       uint2* __restrict__ xfh,
                                                       uint2* __restrict__ xfl) {
    int b = blockIdx.x;
    __shared__ float s[64];
    __shared__ int top[5];
    int tid = threadIdx.x;
    if (tid < 64) s[tid] = g_sim[b * 64 + tid];
    __syncthreads();
    if (tid < 32) {
        for (int k = 0; k < 5; k++) {
            float v = s[tid]; int idx = tid;
            float v2 = s[tid + 32];
            if (v2 > v) { v = v2; idx = tid + 32; }
            for (int o = 16; o > 0; o >>= 1) {
                float ov = __shfl_down_sync(0xffffffffu, v, o);
                int oi = __shfl_down_sync(0xffffffffu, idx, o);
                if (ov > v || (ov == v && oi < idx)) { v = ov; idx = oi; }
            }
            idx = __shfl_sync(0xffffffffu, idx, 0);
            if (tid == 0) top[k] = idx;
            if (tid == 0) s[idx] = -INFINITY;
            __syncwarp();
        }
    }
    __syncthreads();
    const float4* m4 = (const float4*)mem;
    float4* x4 = (float4*)(xflat + (size_t)b * 4096);
    int t0 = top[0] * 1024, t1 = top[1] * 1024, t2 = top[2] * 1024, t3 = top[3] * 1024, t4 = top[4] * 1024;
#pragma unroll
    for (int j = 0; j < 4; j++) {
        int idx = tid + j * 256;
        float4 xv = x4[idx];
        float4 a = m4[t0 + idx], bb = m4[t1 + idx], c = m4[t2 + idx], d = m4[t3 + idx], e = m4[t4 + idx];
        xv.x += 0.02f * (a.x + bb.x + c.x + d.x + e.x);
        xv.y += 0.02f * (a.y + bb.y + c.y + d.y + e.y);
        xv.z += 0.02f * (a.z + bb.z + c.z + d.z + e.z);
        xv.w += 0.02f * (a.w + bb.w + c.w + d.w + e.w);
        x4[idx] = xv;
        uint2 h, l; cvt4(xv, h, l);
        xfh[(size_t)b * 1024 + idx] = h;
        xfl[(size_t)b * 1024 + idx] = l;
    }
}

// ================= proj2 =================
__global__ void __launch_bounds__(256) proj2_kernel(const float* __restrict__ s1,
                                                    const float* __restrict__ Ws2,
                                                    const float* __restrict__ bs2,
                                                    float* __restrict__ proj) {
    __shared__ float w2s[8 * 1024];
    __shared__ float bss[8];
    int tid = threadIdx.x;
    for (int i = tid; i < 8192; i += 256) w2s[i] = Ws2[i];
    if (tid < 8) bss[tid] = bs2[tid];
    __syncthreads();
    int w = tid >> 5, lane = tid & 31;
    int b = blockIdx.x * 8 + w;
    const float4* row = (const float4*)(s1 + (size_t)b * 1024);
    float4 xv[8];
#pragma unroll
    for (int j = 0; j < 8; j++) xv[j] = row[lane + j * 32];
#pragma unroll
    for (int p = 0; p < 8; p++) {
        const float4* wr = (const float4*)(w2s + p * 1024);
        float acc = 0.f;
#pragma unroll
        for (int j = 0; j < 8; j++) {
            float4 wv = wr[lane + j * 32];
            acc += xv[j].x * wv.x + xv[j].y * wv.y + xv[j].z * wv.z + xv[j].w * wv.w;
        }
        for (int o = 16; o > 0; o >>= 1) acc += __shfl_xor_sync(0xffffffffu, acc, o);
        if (lane == 0) proj[(size_t)b * 8 + p] = acc + bss[p];
    }
}

// ================= launch =================
extern "C" void kernel_launch(void* const* d_in, const int* in_sizes, int n_in,
                              void* d_out, int out_size) {
    const float* x      = (const float*)d_in[0];
    const float* W1     = (const float*)d_in[1];
    const float* b1     = (const float*)d_in[2];
    const float* g1     = (const float*)d_in[3];
    const float* beta1  = (const float*)d_in[4];
    const float* W2     = (const float*)d_in[5];
    const float* b2     = (const float*)d_in[6];
    const float* edge_w = (const float*)d_in[7];
    const float* mask   = (const float*)d_in[8];
    const float* Wi     = (const float*)d_in[9];
    const float* bi     = (const float*)d_in[10];
    const float* Wf     = (const float*)d_in[11];
    const float* bf     = (const float*)d_in[12];
    const float* Wslow  = (const float*)d_in[13];
    const float* bslow  = (const float*)d_in[14];
    const float* u      = (const float*)d_in[15];
    const float* Wfast  = (const float*)d_in[16];
    const float* Wo     = (const float*)d_in[17];
    const float* bo     = (const float*)d_in[18];
    const float* gln    = (const float*)d_in[19];
    const float* bln    = (const float*)d_in[20];
    const float* h_prev = (const float*)d_in[21];
    const float* memory = (const float*)d_in[22];
    const float* Wh     = (const float*)d_in[23];
    const float* bh     = (const float*)d_in[24];
    const float* Ws1    = (const float*)d_in[25];
    const float* bs1    = (const float*)d_in[26];
    const float* Ws2    = (const float*)d_in[27];
    const float* bs2    = (const float*)d_in[28];

    float* out    = (float*)d_out;
    float* logits = out;
    float* proj   = out + (size_t)Bn * Ccls;
    float* xflat  = proj + (size_t)Bn * Pp;

    float *p_h1, *p_b2a, *p_xagg, *p_sim, *p_s1, *p_bcat;
    cudaGetSymbolAddress((void**)&p_h1, g_h1);
    cudaGetSymbolAddress((void**)&p_b2a, g_b2a);
    cudaGetSymbolAddress((void**)&p_xagg, g_xagg);
    cudaGetSymbolAddress((void**)&p_sim, g_sim);
    cudaGetSymbolAddress((void**)&p_s1, g_s1);
    cudaGetSymbolAddress((void**)&p_bcat, g_bcat);
    void *p_xh, *p_xl, *p_W1h, *p_W1l, *p_h1h, *p_h1l, *p_W2h, *p_W2l;
    void *p_xfh, *p_xfl, *p_Wcath, *p_memh, *p_meml;
    cudaGetSymbolAddress(&p_xh, g_xh);   cudaGetSymbolAddress(&p_xl, g_xl);
    cudaGetSymbolAddress(&p_W1h, g_W1h); cudaGetSymbolAddress(&p_W1l, g_W1l);
    cudaGetSymbolAddress(&p_h1h, g_h1h); cudaGetSymbolAddress(&p_h1l, g_h1l);
    cudaGetSymbolAddress(&p_W2h, g_W2h); cudaGetSymbolAddress(&p_W2l, g_W2l);
    cudaGetSymbolAddress(&p_xfh, g_xfh); cudaGetSymbolAddress(&p_xfl, g_xfl);
    cudaGetSymbolAddress(&p_Wcath, g_Wcath);
    cudaGetSymbolAddress(&p_memh, g_memh); cudaGetSymbolAddress(&p_meml, g_meml);

    int nsm = 148;
    cudaDeviceGetAttribute(&nsm, cudaDevAttrMultiProcessorCount, 0);
    int persist = 2 * nsm;
    if (persist > 1024) persist = 1024;

    cudaFuncSetAttribute(cell_kernel, cudaFuncAttributeMaxDynamicSharedMemorySize, CELL_SMEM);
    cudaFuncSetAttribute(gemm_mma<4, 3>, cudaFuncAttributeMaxDynamicSharedMemorySize, GSMEM_TOTAL);
    cudaFuncSetAttribute(gemm_mma<4, 2>, cudaFuncAttributeMaxDynamicSharedMemorySize, GSMEM_TOTAL);
    cudaFuncSetAttribute(gemm_mma<4, 1>, cudaFuncAttributeMaxDynamicSharedMemorySize, GSMEM_TOTAL);
    cudaFuncSetAttribute(gemm_mma<2, 3>, cudaFuncAttributeMaxDynamicSharedMemorySize, GSMEM_TOTAL);

    // fused prep
    misc_prep<<<MISC_BLOCKS, 256>>>(x, W1, Ws1, memory, Wh, bh, bs1, b2, edge_w, mask,
                                    Wslow, u, Wfast, Wf, bf, h_prev);
    fold_w2<<<dim3(8, 64), 256>>>(W2, edge_w, mask);

    // stage 1: input projection (3-pass); G2 -> x_agg (2-pass, persistent tiles)
    gemm_mma<4, 3><<<256, 256, GSMEM_TOTAL>>>(
        (const __half*)p_xh, (const __half*)p_xl,
        (const __half*)p_W1h, (const __half*)p_W1l, b1, p_h1, nullptr,
        Fdim, Fdim, Hdim, 0, 0, Hdim / 128, (Hdim / 128) * (Bn / 128));
    ln_gelu_kernel<<<Bn, 256>>>(p_h1, g1, beta1, (uint2*)p_h1h, (uint2*)p_h1l);
    gemm_mma<4, 2><<<persist, 256, GSMEM_TOTAL>>>(
        (const __half*)p_h1h, nullptr,
        (const __half*)p_W2h, (const __half*)p_W2l, p_b2a, p_xagg, nullptr,
        Hdim, Hdim, FLAT, 0, 0, FLAT / 128, (FLAT / 128) * (Bn / 128));

    // stage 2: cells (weights resident, 16 batch tiles per CTA)
    cell_kernel<<<dim3(Nn, CELL_SPLIT), 256, CELL_SMEM>>>(Wi, Wf, Wo, bi, bslow, bo,
                                                          h_prev, gln, bln, xflat,
                                                          (uint32_t*)p_xfh, (uint32_t*)p_xfl);

    // stage 3: retrieval (split-K=8 sim GEMM, atomic accumulate)
    gemm_mma<2, 3><<<dim3(Bn / 128, 1, 8), 256, GSMEM_TOTAL>>>(
        (const __half*)p_xfh, (const __half*)p_xfl,
        (const __half*)p_memh, (const __half*)p_meml, nullptr, p_sim, nullptr,
        FLAT / 8, FLAT, CAP, 0, 1, 1, Bn / 128);
    retrieve_kernel<<<Bn, 256>>>(memory, xflat, (uint2*)p_xfh, (uint2*)p_xfl);

    // stage 4: fused dual head (logits + relu->s1), 1-pass fp16
    gemm_mma<4, 1><<<512, 256, GSMEM_TOTAL>>>(
        (const __half*)p_xfh, nullptr,
        (const __half*)p_Wcath, nullptr, p_bcat, logits, p_s1,
        FLAT, FLAT, 1000, 2, 0, 2048 / 128, (2048 / 128) * (Bn / 128));
    proj2_kernel<<<Bn / 8, 256>>>(p_s1, Ws2, bs2, proj);
}